// round 2
// baseline (speedup 1.0000x reference)
#include <cuda_runtime.h>

#define MAXN 50000

// ---------------- device scratch (no allocations allowed) ----------------
__device__ float g_S   [MAXN * 64];  // segment_sum of x[src] over dst
__device__ float g_deg [MAXN];       // in-degree (float)
__device__ float g_h1  [MAXN * 32];  // q @ WencP1 + b
__device__ float g_h2  [MAXN * 32];  // q @ WencP2 + b
__device__ float g_En  [MAXN * 64];  // E_node
__device__ float g_Enew[MAXN * 64];  // segment_sum(E_node[src] * E_edge)

__device__ __forceinline__ void fma4(float4& acc, float s, const float4& wv) {
    acc.x += s * wv.x; acc.y += s * wv.y; acc.z += s * wv.z; acc.w += s * wv.w;
}

// ---------------- kernel 1: per-node h1/h2 = q @ WencP{1,2} + b ----------
__global__ __launch_bounds__(128) void node_pre(
    const float* __restrict__ x,
    const float* __restrict__ W1, const float* __restrict__ b1,
    const float* __restrict__ W2, const float* __restrict__ b2, int n)
{
    __shared__ float4 sW1[32 * 8], sW2[32 * 8], sb1[8], sb2[8];
    for (int i = threadIdx.x; i < 32 * 8; i += 128) {
        sW1[i] = ((const float4*)W1)[i];
        sW2[i] = ((const float4*)W2)[i];
    }
    if (threadIdx.x < 8) {
        sb1[threadIdx.x] = ((const float4*)b1)[threadIdx.x];
        sb2[threadIdx.x] = ((const float4*)b2)[threadIdx.x];
    }
    __syncthreads();
    int i = blockIdx.x * 128 + threadIdx.x;
    if (i >= n) return;

    float q[32];
    const float4* xp = (const float4*)(x + (size_t)i * 64);  // q = x[:, :32]
#pragma unroll
    for (int k4 = 0; k4 < 8; k4++) {
        float4 v = xp[k4];
        q[4*k4] = v.x; q[4*k4+1] = v.y; q[4*k4+2] = v.z; q[4*k4+3] = v.w;
    }
    float4* o1 = (float4*)(g_h1 + (size_t)i * 32);
    float4* o2 = (float4*)(g_h2 + (size_t)i * 32);
#pragma unroll
    for (int jb = 0; jb < 8; jb++) {
        float4 a1 = sb1[jb], a2 = sb2[jb];
#pragma unroll
        for (int k = 0; k < 32; k++) {
            fma4(a1, q[k], sW1[k*8 + jb]);
            fma4(a2, q[k], sW2[k*8 + jb]);
        }
        o1[jb] = a1;
        o2[jb] = a2;
    }
}

// ---------------- kernel 2: S = segment_sum(x[src], dst), deg ------------
__global__ void edge_scatter(const float* __restrict__ x,
                             const int* __restrict__ src,
                             const int* __restrict__ dst, int e_total)
{
    int t = blockIdx.x * blockDim.x + threadIdx.x;
    int e = t >> 4;
    if (e >= e_total) return;
    int j4 = t & 15;
    int s = __ldg(src + e);
    int d = __ldg(dst + e);
    float4 v = __ldg((const float4*)(x + (size_t)s * 64) + j4);
    float* o = g_S + (size_t)d * 64 + j4 * 4;
    atomicAdd(o + 0, v.x);
    atomicAdd(o + 1, v.y);
    atomicAdd(o + 2, v.z);
    atomicAdd(o + 3, v.w);
    if (j4 == 0) atomicAdd(&g_deg[d], 1.0f);
}

// ------ kernel 3: hK_agg = S[:,32:]@WencK + deg*b ; E_node = mlp3 --------
__global__ __launch_bounds__(128) void node_mid(
    const float* __restrict__ WencK, const float* __restrict__ bencK,
    const float* __restrict__ WK1, const float* __restrict__ bK1,
    const float* __restrict__ WK2, const float* __restrict__ bK2,
    const float* __restrict__ WK3, const float* __restrict__ bK3, int n)
{
    __shared__ float4 sWe[32 * 8],  sbe[8];
    __shared__ float4 sW1[32 * 16], sb1[16];
    __shared__ float4 sW2[64 * 16], sb2[16];
    __shared__ float4 sW3[64 * 16], sb3[16];
    for (int i = threadIdx.x; i < 32 * 8;  i += 128) sWe[i] = ((const float4*)WencK)[i];
    for (int i = threadIdx.x; i < 32 * 16; i += 128) sW1[i] = ((const float4*)WK1)[i];
    for (int i = threadIdx.x; i < 64 * 16; i += 128) sW2[i] = ((const float4*)WK2)[i];
    for (int i = threadIdx.x; i < 64 * 16; i += 128) sW3[i] = ((const float4*)WK3)[i];
    if (threadIdx.x < 8)  sbe[threadIdx.x] = ((const float4*)bencK)[threadIdx.x];
    if (threadIdx.x < 16) {
        sb1[threadIdx.x] = ((const float4*)bK1)[threadIdx.x];
        sb2[threadIdx.x] = ((const float4*)bK2)[threadIdx.x];
        sb3[threadIdx.x] = ((const float4*)bK3)[threadIdx.x];
    }
    __syncthreads();
    int i = blockIdx.x * 128 + threadIdx.x;
    if (i >= n) return;

    float p[32];  // aggregated second half of x
    const float4* Sp = (const float4*)(g_S + (size_t)i * 64);
#pragma unroll
    for (int k4 = 0; k4 < 8; k4++) {
        float4 v = Sp[8 + k4];
        p[4*k4] = v.x; p[4*k4+1] = v.y; p[4*k4+2] = v.z; p[4*k4+3] = v.w;
    }
    float dg = g_deg[i];

    float hK[32];
#pragma unroll
    for (int jb = 0; jb < 8; jb++) {
        float4 b = sbe[jb];
        float4 acc = make_float4(dg*b.x, dg*b.y, dg*b.z, dg*b.w);
#pragma unroll
        for (int k = 0; k < 32; k++) fma4(acc, p[k], sWe[k*8 + jb]);
        hK[4*jb] = acc.x; hK[4*jb+1] = acc.y; hK[4*jb+2] = acc.z; hK[4*jb+3] = acc.w;
    }

    float t1[64];
#pragma unroll
    for (int jb = 0; jb < 16; jb++) {
        float4 acc = sb1[jb];
#pragma unroll
        for (int k = 0; k < 32; k++) fma4(acc, hK[k], sW1[k*16 + jb]);
        t1[4*jb]   = tanhf(acc.x); t1[4*jb+1] = tanhf(acc.y);
        t1[4*jb+2] = tanhf(acc.z); t1[4*jb+3] = tanhf(acc.w);
    }

    float t2[64];
#pragma unroll
    for (int jb = 0; jb < 16; jb++) {
        float4 acc = sb2[jb];
#pragma unroll
        for (int k = 0; k < 64; k++) fma4(acc, t1[k], sW2[k*16 + jb]);
        t2[4*jb]   = fmaxf(acc.x, 0.f); t2[4*jb+1] = fmaxf(acc.y, 0.f);
        t2[4*jb+2] = fmaxf(acc.z, 0.f); t2[4*jb+3] = fmaxf(acc.w, 0.f);
    }

    float4* Eo = (float4*)(g_En + (size_t)i * 64);
#pragma unroll
    for (int jb = 0; jb < 16; jb++) {
        float4 acc = sb3[jb];
#pragma unroll
        for (int k = 0; k < 64; k++) fma4(acc, t2[k], sW3[k*16 + jb]);
        Eo[jb] = acc;
    }
}

// ------ kernel 4 (dominant): per-edge MLP + scatter into E_new -----------
__global__ __launch_bounds__(128) void edge_mlp(
    const int* __restrict__ src, const int* __restrict__ dst,
    const float* __restrict__ WU1, const float* __restrict__ bU1,
    const float* __restrict__ WU2, const float* __restrict__ bU2,
    const float* __restrict__ WU3, const float* __restrict__ bU3, int e_total)
{
    __shared__ float4 sW1[32 * 16], sb1[16];
    __shared__ float4 sW2[64 * 16], sb2[16];
    __shared__ float4 sW3[64 * 16], sb3[16];
    for (int i = threadIdx.x; i < 32 * 16; i += 128) sW1[i] = ((const float4*)WU1)[i];
    for (int i = threadIdx.x; i < 64 * 16; i += 128) sW2[i] = ((const float4*)WU2)[i];
    for (int i = threadIdx.x; i < 64 * 16; i += 128) sW3[i] = ((const float4*)WU3)[i];
    if (threadIdx.x < 16) {
        sb1[threadIdx.x] = ((const float4*)bU1)[threadIdx.x];
        sb2[threadIdx.x] = ((const float4*)bU2)[threadIdx.x];
        sb3[threadIdx.x] = ((const float4*)bU3)[threadIdx.x];
    }
    __syncthreads();

    for (int e = blockIdx.x * blockDim.x + threadIdx.x; e < e_total;
         e += gridDim.x * blockDim.x) {
        int s = __ldg(src + e);
        int d = __ldg(dst + e);

        float eo[32];
        const float4* h1p = (const float4*)(g_h1 + (size_t)s * 32);
        const float4* h2p = (const float4*)(g_h2 + (size_t)d * 32);
#pragma unroll
        for (int k4 = 0; k4 < 8; k4++) {
            float4 a = __ldg(h1p + k4), b = __ldg(h2p + k4);
            eo[4*k4]   = a.x + b.x; eo[4*k4+1] = a.y + b.y;
            eo[4*k4+2] = a.z + b.z; eo[4*k4+3] = a.w + b.w;
        }

        float h[64];
#pragma unroll
        for (int jb = 0; jb < 16; jb++) {
            float4 acc = sb1[jb];
#pragma unroll
            for (int k = 0; k < 32; k++) fma4(acc, eo[k], sW1[k*16 + jb]);
            h[4*jb]   = tanhf(acc.x); h[4*jb+1] = tanhf(acc.y);
            h[4*jb+2] = tanhf(acc.z); h[4*jb+3] = tanhf(acc.w);
        }

        float hh[64];
#pragma unroll
        for (int jb = 0; jb < 16; jb++) {
            float4 acc = sb2[jb];
#pragma unroll
            for (int k = 0; k < 64; k++) fma4(acc, h[k], sW2[k*16 + jb]);
            hh[4*jb]   = fmaxf(acc.x, 0.f); hh[4*jb+1] = fmaxf(acc.y, 0.f);
            hh[4*jb+2] = fmaxf(acc.z, 0.f); hh[4*jb+3] = fmaxf(acc.w, 0.f);
        }

        const float4* Enp = (const float4*)(g_En + (size_t)s * 64);
        float* Ew = g_Enew + (size_t)d * 64;
#pragma unroll
        for (int jb = 0; jb < 16; jb++) {
            float4 acc = sb3[jb];
#pragma unroll
            for (int k = 0; k < 64; k++) fma4(acc, hh[k], sW3[k*16 + jb]);
            float4 En4 = __ldg(Enp + jb);
            atomicAdd(Ew + 4*jb + 0, acc.x * En4.x);
            atomicAdd(Ew + 4*jb + 1, acc.y * En4.y);
            atomicAdd(Ew + 4*jb + 2, acc.z * En4.z);
            atomicAdd(Ew + 4*jb + 3, acc.w * En4.w);
        }
    }
}

// ------ kernel 5: dH = E_new@WH + bH ; d_agg = S@WD[:,32:] + deg*b ; out -
__global__ __launch_bounds__(128) void node_post(
    const float* __restrict__ WH, const float* __restrict__ bH,
    const float* __restrict__ WD, const float* __restrict__ bD,
    float* __restrict__ out, int n)
{
    __shared__ float4 sWH[64 * 16], sbH[16];
    __shared__ float4 sWD[64 * 8],  sbD[8];  // WD[:, 32:]
    for (int i = threadIdx.x; i < 64 * 16; i += 128) sWH[i] = ((const float4*)WH)[i];
    for (int i = threadIdx.x; i < 64 * 8; i += 128) {
        int k = i >> 3, jb = i & 7;
        sWD[i] = ((const float4*)(WD + k * 64 + 32))[jb];
    }
    if (threadIdx.x < 16) sbH[threadIdx.x] = ((const float4*)bH)[threadIdx.x];
    if (threadIdx.x < 8)  sbD[threadIdx.x] = ((const float4*)(bD + 32))[threadIdx.x];
    __syncthreads();
    int i = blockIdx.x * 128 + threadIdx.x;
    if (i >= n) return;

    float En[64];
    const float4* Ep = (const float4*)(g_Enew + (size_t)i * 64);
#pragma unroll
    for (int k4 = 0; k4 < 16; k4++) {
        float4 v = Ep[k4];
        En[4*k4] = v.x; En[4*k4+1] = v.y; En[4*k4+2] = v.z; En[4*k4+3] = v.w;
    }

    float4* op = (float4*)(out + (size_t)i * 64);
    float dlo[32];  // dH[:, :32], needed for the second output half
#pragma unroll
    for (int jb = 0; jb < 16; jb++) {
        float4 acc = sbH[jb];
#pragma unroll
        for (int k = 0; k < 64; k++) fma4(acc, En[k], sWH[k*16 + jb]);
        if (jb >= 8) {
            op[jb - 8] = acc;               // out[:, :32] = dH[:, 32:]
        } else {
            dlo[4*jb] = acc.x; dlo[4*jb+1] = acc.y;
            dlo[4*jb+2] = acc.z; dlo[4*jb+3] = acc.w;
        }
    }

    float S[64];
    const float4* Sp = (const float4*)(g_S + (size_t)i * 64);
#pragma unroll
    for (int k4 = 0; k4 < 16; k4++) {
        float4 v = Sp[k4];
        S[4*k4] = v.x; S[4*k4+1] = v.y; S[4*k4+2] = v.z; S[4*k4+3] = v.w;
    }
    float dg = g_deg[i];
#pragma unroll
    for (int jb = 0; jb < 8; jb++) {
        float4 b = sbD[jb];
        float4 acc = make_float4(dg*b.x, dg*b.y, dg*b.z, dg*b.w);
#pragma unroll
        for (int k = 0; k < 64; k++) fma4(acc, S[k], sWD[k*8 + jb]);
        // out[:, 32:] = -dH[:, :32] - d_agg
        float4 o;
        o.x = -dlo[4*jb]   - acc.x;
        o.y = -dlo[4*jb+1] - acc.y;
        o.z = -dlo[4*jb+2] - acc.z;
        o.w = -dlo[4*jb+3] - acc.w;
        op[8 + jb] = o;
    }
}

// -------------------------------------------------------------------------
extern "C" void kernel_launch(void* const* d_in, const int* in_sizes, int n_in,
                              void* d_out, int out_size)
{
    const float* x      = (const float*)d_in[0];
    const int*   src    = (const int*)  d_in[1];
    const int*   dst    = (const int*)  d_in[2];
    const float* WencK  = (const float*)d_in[3];
    const float* bencK  = (const float*)d_in[4];
    const float* WencP1 = (const float*)d_in[5];
    const float* bencP1 = (const float*)d_in[6];
    const float* WencP2 = (const float*)d_in[7];
    const float* bencP2 = (const float*)d_in[8];
    const float* WK1 = (const float*)d_in[9];
    const float* bK1 = (const float*)d_in[10];
    const float* WK2 = (const float*)d_in[11];
    const float* bK2 = (const float*)d_in[12];
    const float* WK3 = (const float*)d_in[13];
    const float* bK3 = (const float*)d_in[14];
    const float* WU1 = (const float*)d_in[15];
    const float* bU1 = (const float*)d_in[16];
    const float* WU2 = (const float*)d_in[17];
    const float* bU2 = (const float*)d_in[18];
    const float* WU3 = (const float*)d_in[19];
    const float* bU3 = (const float*)d_in[20];
    const float* WH  = (const float*)d_in[21];
    const float* bH  = (const float*)d_in[22];
    const float* WD  = (const float*)d_in[23];
    const float* bD  = (const float*)d_in[24];

    int n = in_sizes[0] / 64;
    int e = in_sizes[1];
    if (n > MAXN) n = MAXN;

    void *pS, *pdeg, *pEnew;
    cudaGetSymbolAddress(&pS,    g_S);
    cudaGetSymbolAddress(&pdeg,  g_deg);
    cudaGetSymbolAddress(&pEnew, g_Enew);
    cudaMemsetAsync(pS,    0, (size_t)n * 64 * sizeof(float));
    cudaMemsetAsync(pdeg,  0, (size_t)n * sizeof(float));
    cudaMemsetAsync(pEnew, 0, (size_t)n * 64 * sizeof(float));

    int nb = (n + 127) / 128;
    node_pre<<<nb, 128>>>(x, WencP1, bencP1, WencP2, bencP2, n);
    edge_scatter<<<((size_t)e * 16 + 255) / 256, 256>>>(x, src, dst, e);
    node_mid<<<nb, 128>>>(WencK, bencK, WK1, bK1, WK2, bK2, WK3, bK3, n);
    edge_mlp<<<444, 128>>>(src, dst, WU1, bU1, WU2, bU2, WU3, bU3, e);
    node_post<<<nb, 128>>>(WH, bH, WD, bD, (float*)d_out, n);
}